// round 12
// baseline (speedup 1.0000x reference)
#include <cuda_runtime.h>

// SpikingNeuronLayer — probe r12: Eigen gebp kc-blocked GEMM, kc = 512.
// Model of reference (XLA:CPU -> Eigen on aarch64):
//   p1 = fused ascending chain over k in [0,512), fresh accumulator
//   p2 = fused ascending chain over k in [512,1024), fresh accumulator
//   dot = fl(p1 + p2)            (gebp writes panel 1, then C += panel 2)
//   I   = fl(dot + b)            (XLA broadcast-add of bias, one rounding)
// Scan: FUSED fma (established closest form), hard reset exact.
// Excluded by prior rounds: plain chain, unfused chain, g4 ladder, bias-in-scan,
// exact GEMM. This is the highest-prior real library structure left standing.

namespace {
constexpr int BATCH  = 64;
constexpr int TSTEPS = 512;
constexpr int INDIM  = 1024;
constexpr int HID    = 1024;
constexpr int M      = BATCH * TSTEPS;   // 32768
constexpr int KSPLIT = 512;              // Eigen kc panel size under test
constexpr float ALPHA = 0.9512294245007140f;  // exp(-1/20) rounded to f32

constexpr int BM = 128, BN = 128, BK = 16;
}

// Scratch for the GEMM output I[M, HID] (134 MB). Static device global: no allocs.
__device__ float g_I[(size_t)M * HID];

__global__ __launch_bounds__(256, 1)
void gemm_bias_kernel(const float* __restrict__ A,   // x  [M, INDIM]
                      const float* __restrict__ B,   // W  [HID, INDIM]
                      const float* __restrict__ bias)
{
    __shared__ float As[BK][BM + 4];
    __shared__ float Bs[BK][BN + 4];

    const int bm  = blockIdx.y * BM;
    const int bn  = blockIdx.x * BN;
    const int tid = threadIdx.x;

    const int tcol = tid & 15;   // across N
    const int trow = tid >> 4;   // across M

    const int lrow = tid >> 2;          // 0..63
    const int lcol = (tid & 3) << 2;    // 0,4,8,12

    // Two accumulator sets: panel 1 (k<512) and panel 2 (k>=512).
    float acc1[8][8], acc2[8][8];
#pragma unroll
    for (int i = 0; i < 8; i++)
#pragma unroll
        for (int j = 0; j < 8; j++) { acc1[i][j] = 0.0f; acc2[i][j] = 0.0f; }

    const float* Ap = A + (size_t)bm * INDIM;
    const float* Bp = B + (size_t)bn * INDIM;

    for (int k0 = 0; k0 < INDIM; k0 += BK) {
        float4 a0 = *(const float4*)(Ap + (size_t)lrow        * INDIM + k0 + lcol);
        float4 a1 = *(const float4*)(Ap + (size_t)(lrow + 64) * INDIM + k0 + lcol);
        float4 b0 = *(const float4*)(Bp + (size_t)lrow        * INDIM + k0 + lcol);
        float4 b1 = *(const float4*)(Bp + (size_t)(lrow + 64) * INDIM + k0 + lcol);

        As[lcol + 0][lrow] = a0.x; As[lcol + 1][lrow] = a0.y;
        As[lcol + 2][lrow] = a0.z; As[lcol + 3][lrow] = a0.w;
        As[lcol + 0][lrow + 64] = a1.x; As[lcol + 1][lrow + 64] = a1.y;
        As[lcol + 2][lrow + 64] = a1.z; As[lcol + 3][lrow + 64] = a1.w;

        Bs[lcol + 0][lrow] = b0.x; Bs[lcol + 1][lrow] = b0.y;
        Bs[lcol + 2][lrow] = b0.z; Bs[lcol + 3][lrow] = b0.w;
        Bs[lcol + 0][lrow + 64] = b1.x; Bs[lcol + 1][lrow + 64] = b1.y;
        Bs[lcol + 2][lrow + 64] = b1.z; Bs[lcol + 3][lrow + 64] = b1.w;

        __syncthreads();

        const bool panel1 = (k0 < KSPLIT);
#pragma unroll
        for (int kk = 0; kk < BK; kk++) {
            float ar[8], br[8];
            *(float4*)&ar[0] = *(const float4*)&As[kk][trow * 8];
            *(float4*)&ar[4] = *(const float4*)&As[kk][trow * 8 + 4];
            *(float4*)&br[0] = *(const float4*)&Bs[kk][tcol * 8];
            *(float4*)&br[4] = *(const float4*)&Bs[kk][tcol * 8 + 4];
            if (panel1) {
#pragma unroll
                for (int i = 0; i < 8; i++)
#pragma unroll
                    for (int j = 0; j < 8; j++)
                        acc1[i][j] = __fmaf_rn(ar[i], br[j], acc1[i][j]);
            } else {
#pragma unroll
                for (int i = 0; i < 8; i++)
#pragma unroll
                    for (int j = 0; j < 8; j++)
                        acc2[i][j] = __fmaf_rn(ar[i], br[j], acc2[i][j]);
            }
        }
        __syncthreads();
    }

    // combine panels (one rounding), then one bias add, write I
    float bj[8];
#pragma unroll
    for (int j = 0; j < 8; j++) bj[j] = bias[bn + tcol * 8 + j];

#pragma unroll
    for (int i = 0; i < 8; i++) {
        const int row = bm + trow * 8 + i;
        float* out = g_I + (size_t)row * HID + bn + tcol * 8;
#pragma unroll
        for (int j = 0; j < 8; j += 4) {
            float4 v;
            v.x = __fadd_rn(__fadd_rn(acc1[i][j + 0], acc2[i][j + 0]), bj[j + 0]);
            v.y = __fadd_rn(__fadd_rn(acc1[i][j + 1], acc2[i][j + 1]), bj[j + 1]);
            v.z = __fadd_rn(__fadd_rn(acc1[i][j + 2], acc2[i][j + 2]), bj[j + 2]);
            v.w = __fadd_rn(__fadd_rn(acc1[i][j + 3], acc2[i][j + 3]), bj[j + 3]);
            *(float4*)(out + j) = v;
        }
    }
}

__global__ __launch_bounds__(256)
void lif_scan_kernel(float* __restrict__ spikes,    // [BATCH, TSTEPS, HID]
                     float* __restrict__ mem_final) // [BATCH, HID]
{
    const int idx = blockIdx.x * blockDim.x + threadIdx.x;  // 0 .. BATCH*HID-1
    const int b = idx / HID;
    const int h = idx - b * HID;

    const float* ip = g_I    + (size_t)b * TSTEPS * HID + h;
    float*       sp = spikes + (size_t)b * TSTEPS * HID + h;

    float mem = 0.0f;
#pragma unroll 4
    for (int t = 0; t < TSTEPS; t++) {
        // FUSED update (established closest form)
        mem = __fmaf_rn(ALPHA, mem, ip[(size_t)t * HID]);
        const float s = (mem >= 1.0f) ? 1.0f : 0.0f;
        sp[(size_t)t * HID] = s;
        mem = mem * (1.0f - s);   // exact: multiplies by 0.0 or 1.0
    }
    mem_final[idx] = mem;
}

extern "C" void kernel_launch(void* const* d_in, const int* in_sizes, int n_in,
                              void* d_out, int out_size)
{
    (void)in_sizes; (void)n_in; (void)out_size;
    const float* x    = (const float*)d_in[0];
    const float* W    = (const float*)d_in[1];
    const float* bias = (const float*)d_in[2];

    float* out    = (float*)d_out;
    float* spikes = out;                              // [B,T,H]
    float* memf   = out + (size_t)M * HID;            // [B,H]

    dim3 grid(HID / BN, M / BM);   // (8, 256)
    gemm_bias_kernel<<<grid, 256>>>(x, W, bias);

    lif_scan_kernel<<<(BATCH * HID) / 256, 256>>>(spikes, memf);
}